// round 15
// baseline (speedup 1.0000x reference)
#include <cuda_runtime.h>
#include <cuda_bf16.h>
#include <stdint.h>
#include <math.h>

#define L_SEQ  2048
#define BATCH  2
#define DMODEL 1024
#define NHEAD  16
#define HDIM   64

#define MROWS (BATCH * L_SEQ)         /* 4096 */

// logits = S_raw * 0.125 / ln(2048); base-2 exponent scale:
#define C2SCALE (0.125f / 7.6246189861593985f * 1.4426950408889634f)

// ---------------- scratch (allocation-free rule: __device__ globals) -------
__device__ __nv_bfloat16 g_xhi[MROWS * DMODEL];
__device__ __nv_bfloat16 g_xlo[MROWS * DMODEL];
__device__ __nv_bfloat16 g_yhi[MROWS * DMODEL];
__device__ __nv_bfloat16 g_ylo[MROWS * DMODEL];
__device__ __nv_bfloat16 g_wqT_hi[3 * DMODEL * DMODEL];   // W_qkv^T [3072,1024]
__device__ __nv_bfloat16 g_wqT_lo[3 * DMODEL * DMODEL];
__device__ __nv_bfloat16 g_woT_hi[DMODEL * DMODEL];       // W_out^T [1024,1024]
__device__ __nv_bfloat16 g_woT_lo[DMODEL * DMODEL];
// head-major attention operands: [B,H,L,128] (x|gate along d), V: [B,H,L,64]
__device__ __nv_bfloat16 g_Qhi[BATCH * NHEAD * L_SEQ * 128];
__device__ __nv_bfloat16 g_Qlo[BATCH * NHEAD * L_SEQ * 128];
__device__ __nv_bfloat16 g_Khi[BATCH * NHEAD * L_SEQ * 128];
__device__ __nv_bfloat16 g_Klo[BATCH * NHEAD * L_SEQ * 128];
__device__ __nv_bfloat16 g_Vhi[BATCH * NHEAD * L_SEQ * 64];
__device__ __nv_bfloat16 g_Vlo[BATCH * NHEAD * L_SEQ * 64];

// ---------------- helpers ---------------------------------------------------
__device__ __forceinline__ uint32_t smem_u32(const void* p) {
    uint32_t a;
    asm("{ .reg .u64 t; cvta.to.shared.u64 t, %1; cvt.u32.u64 %0, t; }"
        : "=r"(a) : "l"(p));
    return a;
}
__device__ __forceinline__ void cp16(uint32_t dst, const void* src) {
    asm volatile("cp.async.cg.shared.global [%0], [%1], 16;"
                 :: "r"(dst), "l"(src) : "memory");
}
__device__ __forceinline__ void ldsm_x4(uint32_t* r, uint32_t addr) {
    asm volatile("ldmatrix.sync.aligned.m8n8.x4.shared.b16 {%0,%1,%2,%3}, [%4];"
                 : "=r"(r[0]), "=r"(r[1]), "=r"(r[2]), "=r"(r[3]) : "r"(addr));
}
__device__ __forceinline__ void ldsm_x4_trans(uint32_t* r, uint32_t addr) {
    asm volatile("ldmatrix.sync.aligned.m8n8.x4.trans.shared.b16 {%0,%1,%2,%3}, [%4];"
                 : "=r"(r[0]), "=r"(r[1]), "=r"(r[2]), "=r"(r[3]) : "r"(addr));
}
__device__ __forceinline__ void mma_16816(float* d, const uint32_t* a, const uint32_t* b) {
    asm volatile(
        "mma.sync.aligned.m16n8k16.row.col.f32.bf16.bf16.f32 "
        "{%0,%1,%2,%3}, {%4,%5,%6,%7}, {%8,%9}, {%0,%1,%2,%3};"
        : "+f"(d[0]), "+f"(d[1]), "+f"(d[2]), "+f"(d[3])
        : "r"(a[0]), "r"(a[1]), "r"(a[2]), "r"(a[3]), "r"(b[0]), "r"(b[1]));
}
__device__ __forceinline__ uint32_t swz(int r, int cu) {
    return (uint32_t)(r * 128 + ((cu ^ (r & 7)) << 4));
}
// 2^t via FMA-pipe polynomial; MUFU-free.
__device__ __forceinline__ float exp2_poly(float t) {
    t = fmaxf(t, -100.0f);
    int i = __float2int_rn(t);
    float f = t - (float)i;                 // [-0.5, 0.5]
    float p = 1.5403530e-4f;
    p = fmaf(p, f, 1.3333558e-3f);
    p = fmaf(p, f, 9.6181291e-3f);
    p = fmaf(p, f, 5.5504109e-2f);
    p = fmaf(p, f, 2.4022651e-1f);
    p = fmaf(p, f, 6.9314718e-1f);
    p = fmaf(p, f, 1.0f);
    return p * __int_as_float((i + 127) << 23);
}
__device__ __forceinline__ float ex2_mufu(float x) {
    float r;
    asm("ex2.approx.f32 %0, %1;" : "=f"(r) : "f"(x));
    return r;
}
// pack 2 floats -> bf16x2 (p0 low) + residual pair
__device__ __forceinline__ void pack_pair(float p0, float p1, uint32_t& hi, uint32_t& lo) {
    asm("cvt.rn.satfinite.bf16x2.f32 %0, %1, %2;" : "=r"(hi) : "f"(p1), "f"(p0));
    __nv_bfloat162 h2 = *(__nv_bfloat162*)&hi;
    float r0 = p0 - __bfloat162float(h2.x);
    float r1 = p1 - __bfloat162float(h2.y);
    asm("cvt.rn.satfinite.bf16x2.f32 %0, %1, %2;" : "=r"(lo) : "f"(r1), "f"(r0));
}
__device__ __forceinline__ void split_store(__nv_bfloat16* hi, __nv_bfloat16* lo,
                                            float v0, float v1) {
    __nv_bfloat162 h2, l2;
    h2.x = __float2bfloat16_rn(v0); h2.y = __float2bfloat16_rn(v1);
    l2.x = __float2bfloat16_rn(v0 - __bfloat162float(h2.x));
    l2.y = __float2bfloat16_rn(v1 - __bfloat162float(h2.y));
    *(__nv_bfloat162*)hi = h2;
    *(__nv_bfloat162*)lo = l2;
}

// ---------------------------------------------------------------------------
// conversion passes
// ---------------------------------------------------------------------------
__global__ void cvt_split_kernel(const float* __restrict__ in,
                                 __nv_bfloat16* __restrict__ hi,
                                 __nv_bfloat16* __restrict__ lo, int n4)
{
    int i = blockIdx.x * blockDim.x + threadIdx.x;
    if (i >= n4) return;
    float4 v = ((const float4*)in)[i];
    split_store(hi + 4 * (size_t)i, lo + 4 * (size_t)i, v.x, v.y);
    split_store(hi + 4 * (size_t)i + 2, lo + 4 * (size_t)i + 2, v.z, v.w);
}

__global__ void cvt_transpose_kernel(const float* __restrict__ W,
                                     __nv_bfloat16* __restrict__ Thi,
                                     __nv_bfloat16* __restrict__ Tlo,
                                     int K, int N)
{
    __shared__ float t[32][33];
    const int n0 = blockIdx.x * 32, k0 = blockIdx.y * 32;
    const int tx = threadIdx.x, ty = threadIdx.y;
#pragma unroll
    for (int j = 0; j < 32; j += 8)
        t[ty + j][tx] = W[(size_t)(k0 + ty + j) * N + n0 + tx];
    __syncthreads();
#pragma unroll
    for (int j = 0; j < 32; j += 8) {
        float v = t[tx][ty + j];
        size_t o = (size_t)(n0 + ty + j) * K + k0 + tx;
        __nv_bfloat16 hv = __float2bfloat16_rn(v);
        Thi[o] = hv;
        Tlo[o] = __float2bfloat16_rn(v - __bfloat162float(hv));
    }
}

// q_g / k_g -> gate halves (d 64..127) of Q/K arrays; q_g scaled by C2SCALE
__global__ void gqk_split_kernel(const float* __restrict__ qg,
                                 const float* __restrict__ kg)
{
    const int row = blockIdx.x;              // b*L + l
    const int t = threadIdx.x;               // 256
    const int h = t >> 4, grp = t & 15;
    const int b = row >> 11, l = row & 2047;
    const size_t so = (size_t)row * DMODEL + h * HDIM + grp * 4;
    float4 q4 = *(const float4*)(qg + so);
    float4 k4 = *(const float4*)(kg + so);
    const size_t base = ((size_t)(b * NHEAD + h) * L_SEQ + l) * 128 + 64 + grp * 4;
    split_store(g_Qhi + base,     g_Qlo + base,     q4.x * C2SCALE, q4.y * C2SCALE);
    split_store(g_Qhi + base + 2, g_Qlo + base + 2, q4.z * C2SCALE, q4.w * C2SCALE);
    split_store(g_Khi + base,     g_Klo + base,     k4.x, k4.y);
    split_store(g_Khi + base + 2, g_Klo + base + 2, k4.z, k4.w);
}

// qkv GEMM epilogue target: route (row, col) -> split Q/K/V arrays
__device__ __forceinline__ void store_qkv_pair(int row, int col, float v0, float v1) {
    const int b = row >> 11, l = row & 2047;
    const int p = col >> 10, c = col & 1023;
    const int h = c >> 6, d = c & 63;
    const size_t base = (size_t)(b * NHEAD + h) * L_SEQ + l;
    if (p == 0) {
        split_store(g_Qhi + base * 128 + d, g_Qlo + base * 128 + d,
                    v0 * C2SCALE, v1 * C2SCALE);
    } else if (p == 1) {
        split_store(g_Khi + base * 128 + d, g_Klo + base * 128 + d, v0, v1);
    } else {
        split_store(g_Vhi + base * 64 + d, g_Vlo + base * 64 + d, v0, v1);
    }
}

// ---------------------------------------------------------------------------
// HMMA split-bf16 GEMM. MODE 0: write fp32 C. MODE 1: qkv split epilogue.
// 128x128 CTA tile, 8 warps (64x32 each), K-chunk 64, cp.async double buffer.
// B fragments loaded pairwise with ldmatrix.x4.
// ---------------------------------------------------------------------------
#define GSTAGE   65536
#define GEMM_SMEM (2 * GSTAGE)

template<int MODE>
__global__ __launch_bounds__(256, 1) void hmma_gemm_kernel(
    int M, int N, int K,
    const __nv_bfloat16* __restrict__ Ahi, const __nv_bfloat16* __restrict__ Alo,
    const __nv_bfloat16* __restrict__ Bhi, const __nv_bfloat16* __restrict__ Blo,
    float* __restrict__ C)
{
    extern __shared__ char smem[];
    const uint32_t sbase = smem_u32(smem);
    const int tid = threadIdx.x;
    const int wid = tid >> 5;
    const int lane = tid & 31;
    const int m0 = blockIdx.y * 128;
    const int n0 = blockIdx.x * 128;
    const int wm = wid & 1;
    const int wn = wid >> 1;

    const __nv_bfloat16* srcs[4] = {
        Ahi + (size_t)m0 * K, Alo + (size_t)m0 * K,
        Bhi + (size_t)n0 * K, Blo + (size_t)n0 * K };

    float acc[4][4][4] = {};
    const int nch = K >> 6;

    auto stage = [&](int c) {
        const int k0 = c << 6;
        const uint32_t sb = sbase + (uint32_t)(c & 1) * GSTAGE;
#pragma unroll
        for (int t = 0; t < 4; t++) {
            const __nv_bfloat16* src = srcs[t] + k0;
#pragma unroll
            for (int i = 0; i < 4; i++) {
                int u = tid + i * 256;
                int r = u >> 3, cu = u & 7;
                cp16(sb + t * 16384 + swz(r, cu), src + (size_t)r * K + cu * 8);
            }
        }
    };

    stage(0);
    asm volatile("cp.async.commit_group;" ::: "memory");

    for (int c = 0; c < nch; c++) {
        if (c + 1 < nch) {
            stage(c + 1);
            asm volatile("cp.async.commit_group;" ::: "memory");
            asm volatile("cp.async.wait_group 1;" ::: "memory");
        } else {
            asm volatile("cp.async.wait_group 0;" ::: "memory");
        }
        __syncthreads();

        const uint32_t sb = sbase + (uint32_t)(c & 1) * GSTAGE;
        const int am = wm * 64, bn = wn * 32;
#pragma unroll
        for (int ks = 0; ks < 4; ks++) {
            uint32_t aH[4][4], aL[4][4], bH2[2][4], bL2[2][4];
            const int acu = ks * 2 + (lane >> 4);
            const int arow = lane & 15;
#pragma unroll
            for (int mi = 0; mi < 4; mi++) {
                int r = am + mi * 16 + arow;
                uint32_t ad = sb + swz(r, acu);
                ldsm_x4(aH[mi], ad);
                ldsm_x4(aL[mi], ad + 16384);
            }
            const int bcu = ks * 2 + ((lane >> 3) & 1);
#pragma unroll
            for (int nip = 0; nip < 2; nip++) {
                int r = bn + nip * 16 + ((lane >> 4) << 3) + (lane & 7);
                uint32_t bd = sb + 32768 + swz(r, bcu);
                ldsm_x4(bH2[nip], bd);
                ldsm_x4(bL2[nip], bd + 16384);
            }
#pragma unroll
            for (int mi = 0; mi < 4; mi++)
#pragma unroll
                for (int ni = 0; ni < 4; ni++) {
                    const uint32_t* bh = &bH2[ni >> 1][(ni & 1) * 2];
                    const uint32_t* bl = &bL2[ni >> 1][(ni & 1) * 2];
                    mma_16816(acc[mi][ni], aH[mi], bh);
                    mma_16816(acc[mi][ni], aH[mi], bl);
                    mma_16816(acc[mi][ni], aL[mi], bh);
                }
        }
        __syncthreads();
    }

#pragma unroll
    for (int mi = 0; mi < 4; mi++) {
        const int row = m0 + wm * 64 + mi * 16 + (lane >> 2);
#pragma unroll
        for (int ni = 0; ni < 4; ni++) {
            const int col = n0 + wn * 32 + ni * 8 + (lane & 3) * 2;
            if (MODE == 0) {
                *(float2*)(C + (size_t)row * N + col) =
                    make_float2(acc[mi][ni][0], acc[mi][ni][1]);
                *(float2*)(C + (size_t)(row + 8) * N + col) =
                    make_float2(acc[mi][ni][2], acc[mi][ni][3]);
            } else {
                store_qkv_pair(row,     col, acc[mi][ni][0], acc[mi][ni][1]);
                store_qkv_pair(row + 8, col, acc[mi][ni][2], acc[mi][ni][3]);
            }
        }
    }
}

// ---------------------------------------------------------------------------
// HMMA flash-attention, kn-split layout. CTA = (qb, h, b); 128 q rows.
// warp = (wq, wk): wq = warp&3 -> 32 q rows; wk = warp>>2 -> 64-col kv half.
// Each warp: mi=2 A tiles x ni=8 B tiles, private m/l/O over its half;
// final merge between wk pairs through smem (reuses K region).
// ---------------------------------------------------------------------------
#define AQH 0
#define AQL 32768
#define AKH 65536
#define AKL 98304
#define AVB 131072
#define AT_SMEM (AVB + 2 * 32768)    /* 196608 */

__global__ __launch_bounds__(256, 1) void attn_hmma_kernel()
{
    extern __shared__ char smem[];
    const uint32_t sb = smem_u32(smem);
    const int tid = threadIdx.x;
    const int warp = tid >> 5, lane = tid & 31;
    const int wq = warp & 3;             // q-row block (32 rows)
    const int wk = warp >> 2;            // kv half (0/1)
    const int knofs = wk * 64;
    const int qb = (int)gridDim.x - 1 - (int)blockIdx.x;   // big blocks first
    const int h = blockIdx.y, b = blockIdx.z;
    const int q0 = qb * 128;
    const size_t hb = (size_t)(b * NHEAD + h) * L_SEQ;

    auto load_kv = [&](int t) {
        const int k0 = t * 128;
#pragma unroll
        for (int i = 0; i < 8; i++) {
            int u = tid + i * 256;
            int r = u >> 4, cu = u & 15;
            uint32_t d = (uint32_t)((cu >> 3) * 16384) + swz(r, cu & 7);
            size_t off = (hb + k0 + r) * 128 + cu * 8;
            cp16(sb + AKH + d, g_Khi + off);
            cp16(sb + AKL + d, g_Klo + off);
        }
        const uint32_t vb = sb + AVB + (uint32_t)(t & 1) * 32768;
#pragma unroll
        for (int i = 0; i < 4; i++) {
            int u = tid + i * 256;
            int r = u >> 3, cu = u & 7;
            size_t off = (hb + k0 + r) * 64 + cu * 8;
            cp16(vb + swz(r, cu), g_Vhi + off);
            cp16(vb + 16384 + swz(r, cu), g_Vlo + off);
        }
    };

    // load Q + first K/V
#pragma unroll
    for (int i = 0; i < 8; i++) {
        int u = tid + i * 256;
        int r = u >> 4, cu = u & 15;
        uint32_t d = (uint32_t)((cu >> 3) * 16384) + swz(r, cu & 7);
        size_t off = (hb + q0 + r) * 128 + cu * 8;
        cp16(sb + AQH + d, g_Qhi + off);
        cp16(sb + AQL + d, g_Qlo + off);
    }
    load_kv(0);
    asm volatile("cp.async.commit_group;" ::: "memory");

    float m[2][2], l[2][2];
#pragma unroll
    for (int mi = 0; mi < 2; mi++) {
        m[mi][0] = -1e30f; m[mi][1] = -1e30f;
        l[mi][0] = 0.f;    l[mi][1] = 0.f;
    }
    float O[2][8][4] = {};

    for (int jt = 0; jt <= qb; jt++) {
        asm volatile("cp.async.wait_group 0;" ::: "memory");
        __syncthreads();

        // ---- S = (Q|Qg) . (K|Kg)^T over own kv half, 3-term split ----
        float s[2][8][4] = {};
#pragma unroll
        for (int ks = 0; ks < 8; ks++) {
            const uint32_t halfo = (uint32_t)((ks >> 2) * 16384);
            const int ks4 = ks & 3;
            uint32_t aH[2][4], aL[2][4];
            const int acu = ks4 * 2 + (lane >> 4);
#pragma unroll
            for (int mi = 0; mi < 2; mi++) {
                int r = wq * 32 + mi * 16 + (lane & 15);
                uint32_t ad = sb + AQH + halfo + swz(r, acu);
                ldsm_x4(aH[mi], ad);
                ldsm_x4(aL[mi], ad + (AQL - AQH));
            }
            const int bcu = ks4 * 2 + ((lane >> 3) & 1);
#pragma unroll
            for (int nip = 0; nip < 4; nip++) {
                uint32_t bH[4], bL[4];
                int r = knofs + nip * 16 + ((lane >> 4) << 3) + (lane & 7);
                uint32_t ka = sb + AKH + halfo + swz(r, bcu);
                ldsm_x4(bH, ka);
                ldsm_x4(bL, ka + (AKL - AKH));
#pragma unroll
                for (int mi = 0; mi < 2; mi++) {
                    mma_16816(s[mi][2 * nip],     aH[mi], bH);
                    mma_16816(s[mi][2 * nip],     aH[mi], bL);
                    mma_16816(s[mi][2 * nip],     aL[mi], bH);
                    mma_16816(s[mi][2 * nip + 1], aH[mi], bH + 2);
                    mma_16816(s[mi][2 * nip + 1], aH[mi], bL + 2);
                    mma_16816(s[mi][2 * nip + 1], aL[mi], bH + 2);
                }
            }
        }
        __syncthreads();                 // all warps done reading K
        if (jt < qb) {
            load_kv(jt + 1);
            asm volatile("cp.async.commit_group;" ::: "memory");
        }

        // ---- causal mask (diagonal tile only) ----
        if (jt == qb) {
#pragma unroll
            for (int mi = 0; mi < 2; mi++) {
                const int r0 = wq * 32 + mi * 16 + (lane >> 2);
#pragma unroll
                for (int ni = 0; ni < 8; ni++) {
                    const int c0 = knofs + ni * 8 + (lane & 3) * 2;
                    if (c0     > r0)     s[mi][ni][0] = -1e30f;
                    if (c0 + 1 > r0)     s[mi][ni][1] = -1e30f;
                    if (c0     > r0 + 8) s[mi][ni][2] = -1e30f;
                    if (c0 + 1 > r0 + 8) s[mi][ni][3] = -1e30f;
                }
            }
        }

        // ---- online softmax (base 2; scale folded into Q) ----
#pragma unroll
        for (int mi = 0; mi < 2; mi++) {
            float tm0 = -1e30f, tm1 = -1e30f;
#pragma unroll
            for (int ni = 0; ni < 8; ni++) {
                tm0 = fmaxf(tm0, fmaxf(s[mi][ni][0], s[mi][ni][1]));
                tm1 = fmaxf(tm1, fmaxf(s[mi][ni][2], s[mi][ni][3]));
            }
            tm0 = fmaxf(tm0, __shfl_xor_sync(0xffffffffu, tm0, 1));
            tm0 = fmaxf(tm0, __shfl_xor_sync(0xffffffffu, tm0, 2));
            tm1 = fmaxf(tm1, __shfl_xor_sync(0xffffffffu, tm1, 1));
            tm1 = fmaxf(tm1, __shfl_xor_sync(0xffffffffu, tm1, 2));
            const float mn0 = fmaxf(m[mi][0], tm0), mn1 = fmaxf(m[mi][1], tm1);
            const float al0 = ex2_mufu(m[mi][0] - mn0);
            const float al1 = ex2_mufu(m[mi][1] - mn1);
            m[mi][0] = mn0; m[mi][1] = mn1;
            float rs0 = 0.f, rs1 = 0.f;
#pragma unroll
            for (int ni = 0; ni < 8; ni++) {
                s[mi][ni][0] = exp2_poly(s[mi][ni][0] - mn0); rs0 += s[mi][ni][0];
                s[mi][ni][1] = exp2_poly(s[mi][ni][1] - mn0); rs0 += s[mi][ni][1];
                s[mi][ni][2] = exp2_poly(s[mi][ni][2] - mn1); rs1 += s[mi][ni][2];
                s[mi][ni][3] = exp2_poly(s[mi][ni][3] - mn1); rs1 += s[mi][ni][3];
            }
            l[mi][0] = l[mi][0] * al0 + rs0;
            l[mi][1] = l[mi][1] * al1 + rs1;
#pragma unroll
            for (int ni = 0; ni < 8; ni++) {
                O[mi][ni][0] *= al0; O[mi][ni][1] *= al0;
                O[mi][ni][2] *= al1; O[mi][ni][3] *= al1;
            }
        }

        // ---- O += P . V over own 64 kv rows (3-term split) ----
        const uint32_t vb = sb + AVB + (uint32_t)(jt & 1) * 32768;
#pragma unroll
        for (int kk = 0; kk < 4; kk++) {
            uint32_t aPh[2][4], aPl[2][4];
#pragma unroll
            for (int mi = 0; mi < 2; mi++) {
                pack_pair(s[mi][2 * kk][0],     s[mi][2 * kk][1],     aPh[mi][0], aPl[mi][0]);
                pack_pair(s[mi][2 * kk][2],     s[mi][2 * kk][3],     aPh[mi][1], aPl[mi][1]);
                pack_pair(s[mi][2 * kk + 1][0], s[mi][2 * kk + 1][1], aPh[mi][2], aPl[mi][2]);
                pack_pair(s[mi][2 * kk + 1][2], s[mi][2 * kk + 1][3], aPh[mi][3], aPl[mi][3]);
            }
            const int vr = knofs + kk * 16 + (lane & 15);
#pragma unroll
            for (int nip = 0; nip < 4; nip++) {
                uint32_t bVh[4], bVl[4];
                const int vcu = 2 * nip + (lane >> 4);
                uint32_t va = vb + swz(vr, vcu);
                ldsm_x4_trans(bVh, va);
                ldsm_x4_trans(bVl, va + 16384);
#pragma unroll
                for (int mi = 0; mi < 2; mi++) {
                    mma_16816(O[mi][2 * nip],     aPh[mi], bVh);
                    mma_16816(O[mi][2 * nip],     aPh[mi], bVl);
                    mma_16816(O[mi][2 * nip],     aPl[mi], bVh);
                    mma_16816(O[mi][2 * nip + 1], aPh[mi], bVh + 2);
                    mma_16816(O[mi][2 * nip + 1], aPh[mi], bVl + 2);
                    mma_16816(O[mi][2 * nip + 1], aPl[mi], bVh + 2);
                }
            }
        }
    }

    // ---- full-row l (sum across lane quad) ----
#pragma unroll
    for (int mi = 0; mi < 2; mi++) {
        l[mi][0] += __shfl_xor_sync(0xffffffffu, l[mi][0], 1);
        l[mi][0] += __shfl_xor_sync(0xffffffffu, l[mi][0], 2);
        l[mi][1] += __shfl_xor_sync(0xffffffffu, l[mi][1], 1);
        l[mi][1] += __shfl_xor_sync(0xffffffffu, l[mi][1], 2);
    }

    // ---- merge kv halves through smem (reuse K region) ----
    float*  Obuf = (float*)(smem + AKH);          // [128][64] fp32 = 32KB
    float2* mlb  = (float2*)(smem + AKH + 32768); // [128] (m,l)
    __syncthreads();
    if (wk == 1) {
#pragma unroll
        for (int mi = 0; mi < 2; mi++) {
            const int r = wq * 32 + mi * 16 + (lane >> 2);
#pragma unroll
            for (int ni = 0; ni < 8; ni++) {
                const int cc = ni * 8 + (lane & 3) * 2;
                *(float2*)&Obuf[r * 64 + cc]       = make_float2(O[mi][ni][0], O[mi][ni][1]);
                *(float2*)&Obuf[(r + 8) * 64 + cc] = make_float2(O[mi][ni][2], O[mi][ni][3]);
            }
            if ((lane & 3) == 0) {
                mlb[r]     = make_float2(m[mi][0], l[mi][0]);
                mlb[r + 8] = make_float2(m[mi][1], l[mi][1]);
            }
        }
    }
    __syncthreads();
    if (wk == 0) {
#pragma unroll
        for (int mi = 0; mi < 2; mi++) {
            const int r = wq * 32 + mi * 16 + (lane >> 2);
            const float2 mlB0 = mlb[r], mlB1 = mlb[r + 8];
            const float mm0 = fmaxf(m[mi][0], mlB0.x);
            const float mm1 = fmaxf(m[mi][1], mlB1.x);
            const float aA0 = ex2_mufu(m[mi][0] - mm0), aB0 = ex2_mufu(mlB0.x - mm0);
            const float aA1 = ex2_mufu(m[mi][1] - mm1), aB1 = ex2_mufu(mlB1.x - mm1);
            const float inv0 = 1.0f / (l[mi][0] * aA0 + mlB0.y * aB0);
            const float inv1 = 1.0f / (l[mi][1] * aA1 + mlB1.y * aB1);
            const int grow = b * L_SEQ + q0 + r;
#pragma unroll
            for (int ni = 0; ni < 8; ni++) {
                const int cc = ni * 8 + (lane & 3) * 2;
                float2 ob0 = *(float2*)&Obuf[r * 64 + cc];
                float2 ob1 = *(float2*)&Obuf[(r + 8) * 64 + cc];
                const float v00 = (O[mi][ni][0] * aA0 + ob0.x * aB0) * inv0;
                const float v01 = (O[mi][ni][1] * aA0 + ob0.y * aB0) * inv0;
                const float v10 = (O[mi][ni][2] * aA1 + ob1.x * aB1) * inv1;
                const float v11 = (O[mi][ni][3] * aA1 + ob1.y * aB1) * inv1;
                const int d = h * HDIM + cc;
                size_t o0 = (size_t)grow * DMODEL + d;
                size_t o1 = (size_t)(grow + 8) * DMODEL + d;
                split_store(g_yhi + o0, g_ylo + o0, v00, v01);
                split_store(g_yhi + o1, g_ylo + o1, v10, v11);
            }
        }
    }
}

// ---------------------------------------------------------------------------
extern "C" void kernel_launch(void* const* d_in, const int* in_sizes, int n_in,
                              void* d_out, int out_size)
{
    const float* x     = (const float*)d_in[0];
    const float* q_g   = (const float*)d_in[1];
    const float* k_g   = (const float*)d_in[2];
    const float* W_qkv = (const float*)d_in[3];
    const float* W_out = (const float*)d_in[4];
    float* out = (float*)d_out;

    __nv_bfloat16 *xhi, *xlo, *yhi, *ylo, *wqh, *wql, *woh, *wol;
    cudaGetSymbolAddress((void**)&xhi, g_xhi);
    cudaGetSymbolAddress((void**)&xlo, g_xlo);
    cudaGetSymbolAddress((void**)&yhi, g_yhi);
    cudaGetSymbolAddress((void**)&ylo, g_ylo);
    cudaGetSymbolAddress((void**)&wqh, g_wqT_hi);
    cudaGetSymbolAddress((void**)&wql, g_wqT_lo);
    cudaGetSymbolAddress((void**)&woh, g_woT_hi);
    cudaGetSymbolAddress((void**)&wol, g_woT_lo);

    cudaFuncSetAttribute(hmma_gemm_kernel<0>,
                         cudaFuncAttributeMaxDynamicSharedMemorySize, GEMM_SMEM);
    cudaFuncSetAttribute(hmma_gemm_kernel<1>,
                         cudaFuncAttributeMaxDynamicSharedMemorySize, GEMM_SMEM);
    cudaFuncSetAttribute(attn_hmma_kernel,
                         cudaFuncAttributeMaxDynamicSharedMemorySize, AT_SMEM);

    // 0) splits / transposes
    {
        int n4 = MROWS * DMODEL / 4;
        cvt_split_kernel<<<(n4 + 255) / 256, 256>>>(x, xhi, xlo, n4);
        dim3 blk(32, 8);
        cvt_transpose_kernel<<<dim3(3 * DMODEL / 32, DMODEL / 32), blk>>>(
            W_qkv, wqh, wql, DMODEL, 3 * DMODEL);
        cvt_transpose_kernel<<<dim3(DMODEL / 32, DMODEL / 32), blk>>>(
            W_out, woh, wol, DMODEL, DMODEL);
        gqk_split_kernel<<<MROWS, 256>>>(q_g, k_g);
    }

    // 1) qkv projection -> split head-major Q/K/V (epilogue fused)
    hmma_gemm_kernel<1><<<dim3(3 * DMODEL / 128, MROWS / 128), 256, GEMM_SMEM>>>(
        MROWS, 3 * DMODEL, DMODEL, xhi, xlo, wqh, wql, nullptr);

    // 2) attention (HMMA flash, kn-split)
    attn_hmma_kernel<<<dim3(L_SEQ / 128, NHEAD, BATCH), 256, AT_SMEM>>>();

    // 3) out = y @ W_out
    hmma_gemm_kernel<0><<<dim3(DMODEL / 128, MROWS / 128), 256, GEMM_SMEM>>>(
        MROWS, DMODEL, DMODEL, yhi, ylo, woh, wol, out);
}